// round 5
// baseline (speedup 1.0000x reference)
#include <cuda_runtime.h>
#include <stdint.h>

// Resolutions: floor(16 * growth^i) replicating numpy's float64 pipeline.
// Level 15: 16*growth^15 lands just below 4096 in float64 -> floor = 4095.
__constant__ float c_res[16] = {
    16.f, 23.f, 33.f, 48.f, 70.f, 101.f, 147.f, 212.f,
    307.f, 445.f, 645.f, 933.f, 1351.f, 1955.f, 2830.f, 4095.f
};

#define HG_P2 2654435761u
#define HG_P3 805459861u
#define HG_MASK 0x7FFFFu   // T-1, T = 2^19

// Dense smem grids for coarse levels (points in [0,1): ix+1 <= res).
#define L0_SIDE 17
#define L0_N    (17*17*17)     // 4913
#define L1_SIDE 24
#define L1_N    (24*24*24)     // 13824
#define SMEM_ENTRIES (L0_N + L1_N)              // 18737 float2
#define SMEM_BYTES   (SMEM_ENTRIES * 8)         // 149896 B

#define NWARPS        32
#define GATHER_WARPS  30   // warps 0..29: levels 2..15 via LDG
#define SMEM_WARPS    2    // warps 30..31: levels 0..1 via LDS

__device__ __forceinline__ void interp_store(
    float2 f000, float2 f001, float2 f010, float2 f011,
    float2 f100, float2 f101, float2 f110, float2 f111,
    float wx, float wy, float wz, float2* __restrict__ dst)
{
    float wx0 = __fadd_rn(1.0f, -wx), wx1 = wx;
    float wy0 = __fadd_rn(1.0f, -wy), wy1 = wy;
    float wz0 = __fadd_rn(1.0f, -wz), wz1 = wz;

    // w = (x_term * y_term) * z_term, left-associated RN — matches reference.
    float w000 = __fmul_rn(__fmul_rn(wx0, wy0), wz0);
    float w001 = __fmul_rn(__fmul_rn(wx0, wy0), wz1);
    float w010 = __fmul_rn(__fmul_rn(wx0, wy1), wz0);
    float w011 = __fmul_rn(__fmul_rn(wx0, wy1), wz1);
    float w100 = __fmul_rn(__fmul_rn(wx1, wy0), wz0);
    float w101 = __fmul_rn(__fmul_rn(wx1, wy0), wz1);
    float w110 = __fmul_rn(__fmul_rn(wx1, wy1), wz0);
    float w111 = __fmul_rn(__fmul_rn(wx1, wy1), wz1);

    // Reference corner order, separate RN mul + add (no FMA) — bit-exact.
    float a0 = 0.0f, a1 = 0.0f;
    a0 = __fadd_rn(a0, __fmul_rn(f000.x, w000));  a1 = __fadd_rn(a1, __fmul_rn(f000.y, w000));
    a0 = __fadd_rn(a0, __fmul_rn(f001.x, w001));  a1 = __fadd_rn(a1, __fmul_rn(f001.y, w001));
    a0 = __fadd_rn(a0, __fmul_rn(f010.x, w010));  a1 = __fadd_rn(a1, __fmul_rn(f010.y, w010));
    a0 = __fadd_rn(a0, __fmul_rn(f011.x, w011));  a1 = __fadd_rn(a1, __fmul_rn(f011.y, w011));
    a0 = __fadd_rn(a0, __fmul_rn(f100.x, w100));  a1 = __fadd_rn(a1, __fmul_rn(f100.y, w100));
    a0 = __fadd_rn(a0, __fmul_rn(f101.x, w101));  a1 = __fadd_rn(a1, __fmul_rn(f101.y, w101));
    a0 = __fadd_rn(a0, __fmul_rn(f110.x, w110));  a1 = __fadd_rn(a1, __fmul_rn(f110.y, w110));
    a0 = __fadd_rn(a0, __fmul_rn(f111.x, w111));  a1 = __fadd_rn(a1, __fmul_rn(f111.y, w111));

    *dst = make_float2(a0, a1);
}

__global__ __launch_bounds__(1024, 1) void hashgrid_kernel(
    const float* __restrict__ x,
    const float* __restrict__ table,
    float2* __restrict__ out,
    int n_points)
{
    extern __shared__ float2 sm[];

    // ---- Preload levels 0 and 1 into dense smem grids (all warps). ----
    // sm[dense(cell)] = table[hash(cell)] -- exact, collisions irrelevant.
    for (int c = threadIdx.x; c < L0_N; c += blockDim.x) {
        int iz = c % L0_SIDE;
        int r  = c / L0_SIDE;
        int iy = r % L0_SIDE;
        int ix = r / L0_SIDE;
        uint32_t h = ((uint32_t)ix ^ ((uint32_t)iy * HG_P2) ^ ((uint32_t)iz * HG_P3)) & HG_MASK;
        sm[c] = __ldg((const float2*)table + h);
    }
    for (int c = threadIdx.x; c < L1_N; c += blockDim.x) {
        int iz = c % L1_SIDE;
        int r  = c / L1_SIDE;
        int iy = r % L1_SIDE;
        int ix = r / L1_SIDE;
        uint32_t h = ((uint32_t)ix ^ ((uint32_t)iy * HG_P2) ^ ((uint32_t)iz * HG_P3)) & HG_MASK;
        sm[L0_N + c] = __ldg((const float2*)table + (h + (1u << 19)));
    }
    __syncthreads();
    // After this point warps own disjoint task ranges: no further block syncs.

    int warp = threadIdx.x >> 5;
    int lane = threadIdx.x & 31;

    if (warp < GATHER_WARPS) {
        // ================= Gather warps: levels 2..15 via LDG =================
        unsigned gwid   = (unsigned)blockIdx.x * GATHER_WARPS + warp;
        unsigned stride = (unsigned)gridDim.x * GATHER_WARPS * 32u;
        unsigned total  = (unsigned)n_points * 14u;

        for (unsigned task = gwid * 32u + lane; task < total; task += stride) {
            unsigned p   = task / 14u;
            int      lvl = 2 + (int)(task - p * 14u);

            // ~14 lanes share a point: broadcast loads.
            float px = x[3 * p + 0];
            float py = x[3 * p + 1];
            float pz = x[3 * p + 2];

            float res = c_res[lvl];
            float sx = __fmul_rn(px, res);
            float sy = __fmul_rn(py, res);
            float sz = __fmul_rn(pz, res);
            float fx = floorf(sx);
            float fy = floorf(sy);
            float fz = floorf(sz);
            float wx = __fadd_rn(sx, -fx);
            float wy = __fadd_rn(sy, -fy);
            float wz = __fadd_rn(sz, -fz);

            uint32_t hx0 = (uint32_t)(int)fx;
            uint32_t hx1 = hx0 + 1u;
            uint32_t hy0 = (uint32_t)(int)fy * HG_P2;
            uint32_t hy1 = hy0 + HG_P2;
            uint32_t hz0 = (uint32_t)(int)fz * HG_P3;
            uint32_t hz1 = hz0 + HG_P3;

            const float2* tab = (const float2*)table + ((uint32_t)lvl << 19);

            float2 f000 = __ldg(tab + ((hx0 ^ hy0 ^ hz0) & HG_MASK));
            float2 f001 = __ldg(tab + ((hx0 ^ hy0 ^ hz1) & HG_MASK));
            float2 f010 = __ldg(tab + ((hx0 ^ hy1 ^ hz0) & HG_MASK));
            float2 f011 = __ldg(tab + ((hx0 ^ hy1 ^ hz1) & HG_MASK));
            float2 f100 = __ldg(tab + ((hx1 ^ hy0 ^ hz0) & HG_MASK));
            float2 f101 = __ldg(tab + ((hx1 ^ hy0 ^ hz1) & HG_MASK));
            float2 f110 = __ldg(tab + ((hx1 ^ hy1 ^ hz0) & HG_MASK));
            float2 f111 = __ldg(tab + ((hx1 ^ hy1 ^ hz1) & HG_MASK));

            interp_store(f000, f001, f010, f011, f100, f101, f110, f111,
                         wx, wy, wz, &out[p * 16u + (unsigned)lvl]);
        }
    } else {
        // ================= Smem warps: levels 0..1 via LDS ====================
        unsigned swid   = (unsigned)blockIdx.x * SMEM_WARPS + (warp - GATHER_WARPS);
        unsigned stride = (unsigned)gridDim.x * SMEM_WARPS * 32u;
        unsigned total  = (unsigned)n_points * 2u;

        for (unsigned task = swid * 32u + lane; task < total; task += stride) {
            unsigned p   = task >> 1;
            int      lvl = (int)(task & 1u);

            float px = x[3 * p + 0];
            float py = x[3 * p + 1];
            float pz = x[3 * p + 2];

            float res = c_res[lvl];
            float sx = __fmul_rn(px, res);
            float sy = __fmul_rn(py, res);
            float sz = __fmul_rn(pz, res);
            float fx = floorf(sx);
            float fy = floorf(sy);
            float fz = floorf(sz);
            float wx = __fadd_rn(sx, -fx);
            float wy = __fadd_rn(sy, -fy);
            float wz = __fadd_rn(sz, -fz);

            int ix = (int)fx;
            int iy = (int)fy;
            int iz = (int)fz;

            // Dense direct indexing -- no hash needed, collisions pre-resolved.
            int side = (lvl == 0) ? L0_SIDE : L1_SIDE;
            const float2* stab = sm + ((lvl == 0) ? 0 : L0_N);
            int s2   = side * side;
            int base = (ix * side + iy) * side + iz;

            float2 f000 = stab[base];
            float2 f001 = stab[base + 1];
            float2 f010 = stab[base + side];
            float2 f011 = stab[base + side + 1];
            float2 f100 = stab[base + s2];
            float2 f101 = stab[base + s2 + 1];
            float2 f110 = stab[base + s2 + side];
            float2 f111 = stab[base + s2 + side + 1];

            interp_store(f000, f001, f010, f011, f100, f101, f110, f111,
                         wx, wy, wz, &out[p * 16u + (unsigned)lvl]);
        }
    }
}

extern "C" void kernel_launch(void* const* d_in, const int* in_sizes, int n_in,
                              void* d_out, int out_size)
{
    // Defensive input-order resolution: x (N*3) is smaller than table (T*L*F).
    const float* a = (const float*)d_in[0];
    const float* b = (const float*)d_in[1];
    int sa = in_sizes[0], sb = in_sizes[1];

    const float* x;
    const float* table;
    int x_elems;
    if (sa <= sb) { x = a; table = b; x_elems = sa; }
    else          { x = b; table = a; x_elems = sb; }

    float2* out = (float2*)d_out;
    int n_points = x_elems / 3;

    static bool attr_set = false;  // idempotent attribute set (not a work guard)
    if (!attr_set) {
        cudaFuncSetAttribute(hashgrid_kernel,
                             cudaFuncAttributeMaxDynamicSharedMemorySize, SMEM_BYTES);
        attr_set = true;
    }

    int dev = 0, sms = 148;
    cudaGetDevice(&dev);
    cudaDeviceGetAttribute(&sms, cudaDevAttrMultiProcessorCount, dev);

    // One persistent wave: 1 CTA/SM (150KB smem), 1024 threads.
    hashgrid_kernel<<<sms, 1024, SMEM_BYTES>>>(x, table, out, n_points);
}